// round 5
// baseline (speedup 1.0000x reference)
#include <cuda_runtime.h>
#include <cstdint>

#define D_MODEL 1024
#define NUM_HEADS 16
#define HEAD_DIM 64
#define BATCH 4
#define SEQ 2048
#define MTOT (BATCH*SEQ)

// ---------------- scratch (device globals: no allocs allowed) ----------------
__device__ float g_q[(size_t)MTOT * D_MODEL];
__device__ float g_k[(size_t)MTOT * D_MODEL];
__device__ float g_v[(size_t)MTOT * D_MODEL];
__device__ float g_attn[(size_t)MTOT * D_MODEL];

// ---------------- helpers ----------------------------------------------------
__device__ __forceinline__ uint32_t f2tf32(float x) {
    uint32_t r;
    asm("cvt.rna.tf32.f32 %0, %1;" : "=r"(r) : "f"(x));
    return r;
}
__device__ __forceinline__ float ex2(float x) {
    float y;
    asm("ex2.approx.f32 %0, %1;" : "=f"(y) : "f"(x));
    return y;
}

#define LDMATRIX_X4(R0, R1, R2, R3, addr)                                       \
    asm volatile("ldmatrix.sync.aligned.m8n8.x4.shared.b16 {%0,%1,%2,%3}, [%4];" \
                 : "=r"(R0), "=r"(R1), "=r"(R2), "=r"(R3) : "r"(addr))

#define MMA_TF32(C0, C1, C2, C3, A0, A1, A2, A3, B0, B1)                        \
    asm volatile("mma.sync.aligned.m16n8k8.row.col.f32.tf32.tf32.f32 "          \
                 "{%0,%1,%2,%3},{%4,%5,%6,%7},{%8,%9},{%0,%1,%2,%3};"           \
                 : "+f"(C0), "+f"(C1), "+f"(C2), "+f"(C3)                       \
                 : "r"(A0), "r"(A1), "r"(A2), "r"(A3), "r"(B0), "r"(B1))

// ---------------- TF32 tensor-core GEMM: C = A[M,K] @ W[K,N] + bias ----------
// BM=128, BN=64, BK=16. 8 warps 4(m)x2(n), warp tile 32x32.
// Double-buffered smem: one __syncthreads per k-iteration.
#define GBM 128
#define GBN 64
#define GBK 16
#define SA 20
#define SW 20

__global__ __launch_bounds__(256, 2)
void gemm_tf32_kernel(const float* __restrict__ A,
                      const float* __restrict__ W,
                      const float* __restrict__ bias,
                      float* __restrict__ C,
                      int M, int N, int K)
{
    __shared__ float As[2][GBM * SA];
    __shared__ float Ws[2][GBN * SW];

    const int tid  = threadIdx.x;
    const int lane = tid & 31;
    const int wid  = tid >> 5;
    const int wm   = wid >> 1;
    const int wn   = wid & 1;
    const int row0 = blockIdx.y * GBM;
    const int col0 = blockIdx.x * GBN;

    const int ar  = tid >> 2;
    const int akq = (tid & 3) << 2;
    const int wnx = tid & 63;
    const int wkg = (tid >> 6) << 2;

    const int lj = lane >> 3;
    const int lr = lane & 7;
    const uint32_t as_base = (uint32_t)__cvta_generic_to_shared(&As[0][0]);
    const uint32_t ws_base = (uint32_t)__cvta_generic_to_shared(&Ws[0][0]);
    const uint32_t abuf = GBM * SA * 4;   // byte offset between A buffers
    const uint32_t wbuf = GBN * SW * 4;
    uint32_t a_addr[2], b_addr[2];
#pragma unroll
    for (int i = 0; i < 2; ++i)
        a_addr[i] = as_base + (((wm * 32 + i * 16 + lr + 8 * (lj & 1)) * SA
                               + 4 * (lj >> 1)) << 2);
#pragma unroll
    for (int t = 0; t < 2; ++t)
        b_addr[t] = ws_base + (((wn * 32 + t * 16 + lr + 8 * (lj >> 1)) * SW
                               + 4 * (lj & 1)) << 2);

    float acc[2][4][4];
#pragma unroll
    for (int i = 0; i < 2; ++i)
#pragma unroll
        for (int j = 0; j < 4; ++j)
#pragma unroll
            for (int e = 0; e < 4; ++e) acc[i][j][e] = 0.f;

    const float* Ap0 = A + (size_t)(row0 + ar) * K + akq;
    const float* Ap1 = A + (size_t)(row0 + 64 + ar) * K + akq;
    const float* Wp  = W + (size_t)wkg * N + col0 + wnx;

    float4 pa0, pa1;
    float pw0, pw1, pw2, pw3;

    // prologue: tile 0 -> buffer 0
    pa0 = *(const float4*)Ap0;
    pa1 = *(const float4*)Ap1;
    pw0 = Wp[0]; pw1 = Wp[(size_t)N]; pw2 = Wp[(size_t)2 * N]; pw3 = Wp[(size_t)3 * N];
    {
        float4 s0, s1, sw;
        s0.x = __uint_as_float(f2tf32(pa0.x)); s0.y = __uint_as_float(f2tf32(pa0.y));
        s0.z = __uint_as_float(f2tf32(pa0.z)); s0.w = __uint_as_float(f2tf32(pa0.w));
        s1.x = __uint_as_float(f2tf32(pa1.x)); s1.y = __uint_as_float(f2tf32(pa1.y));
        s1.z = __uint_as_float(f2tf32(pa1.z)); s1.w = __uint_as_float(f2tf32(pa1.w));
        sw.x = __uint_as_float(f2tf32(pw0));   sw.y = __uint_as_float(f2tf32(pw1));
        sw.z = __uint_as_float(f2tf32(pw2));   sw.w = __uint_as_float(f2tf32(pw3));
        *(float4*)&As[0][ar * SA + akq]        = s0;
        *(float4*)&As[0][(64 + ar) * SA + akq] = s1;
        *(float4*)&Ws[0][wnx * SW + wkg]       = sw;
    }
    __syncthreads();

    int cur = 0;
    for (int k0 = 0; k0 < K; k0 += GBK, cur ^= 1) {
        const bool has_next = (k0 + GBK) < K;
        if (has_next) {
            pa0 = *(const float4*)(Ap0 + k0 + GBK);
            pa1 = *(const float4*)(Ap1 + k0 + GBK);
            const float* wp = Wp + (size_t)(k0 + GBK) * N;
            pw0 = wp[0]; pw1 = wp[(size_t)N]; pw2 = wp[(size_t)2 * N]; pw3 = wp[(size_t)3 * N];
        }

        const uint32_t ao = cur ? abuf : 0u;
        const uint32_t wo = cur ? wbuf : 0u;
#pragma unroll
        for (int ks = 0; ks < GBK; ks += 8) {
            uint32_t a[2][4], bq[2][4];
            LDMATRIX_X4(a[0][0], a[0][1], a[0][2], a[0][3], a_addr[0] + ao + (ks << 2));
            LDMATRIX_X4(a[1][0], a[1][1], a[1][2], a[1][3], a_addr[1] + ao + (ks << 2));
            LDMATRIX_X4(bq[0][0], bq[0][1], bq[0][2], bq[0][3], b_addr[0] + wo + (ks << 2));
            LDMATRIX_X4(bq[1][0], bq[1][1], bq[1][2], bq[1][3], b_addr[1] + wo + (ks << 2));
#pragma unroll
            for (int i = 0; i < 2; ++i) {
                MMA_TF32(acc[i][0][0], acc[i][0][1], acc[i][0][2], acc[i][0][3],
                         a[i][0], a[i][1], a[i][2], a[i][3], bq[0][0], bq[0][1]);
                MMA_TF32(acc[i][1][0], acc[i][1][1], acc[i][1][2], acc[i][1][3],
                         a[i][0], a[i][1], a[i][2], a[i][3], bq[0][2], bq[0][3]);
                MMA_TF32(acc[i][2][0], acc[i][2][1], acc[i][2][2], acc[i][2][3],
                         a[i][0], a[i][1], a[i][2], a[i][3], bq[1][0], bq[1][1]);
                MMA_TF32(acc[i][3][0], acc[i][3][1], acc[i][3][2], acc[i][3][3],
                         a[i][0], a[i][1], a[i][2], a[i][3], bq[1][2], bq[1][3]);
            }
        }

        if (has_next) {
            const int nxt = cur ^ 1;
            float4 s0, s1, sw;
            s0.x = __uint_as_float(f2tf32(pa0.x)); s0.y = __uint_as_float(f2tf32(pa0.y));
            s0.z = __uint_as_float(f2tf32(pa0.z)); s0.w = __uint_as_float(f2tf32(pa0.w));
            s1.x = __uint_as_float(f2tf32(pa1.x)); s1.y = __uint_as_float(f2tf32(pa1.y));
            s1.z = __uint_as_float(f2tf32(pa1.z)); s1.w = __uint_as_float(f2tf32(pa1.w));
            sw.x = __uint_as_float(f2tf32(pw0));   sw.y = __uint_as_float(f2tf32(pw1));
            sw.z = __uint_as_float(f2tf32(pw2));   sw.w = __uint_as_float(f2tf32(pw3));
            *(float4*)&As[nxt][ar * SA + akq]        = s0;
            *(float4*)&As[nxt][(64 + ar) * SA + akq] = s1;
            *(float4*)&Ws[nxt][wnx * SW + wkg]       = sw;
        }
        __syncthreads();
    }

#pragma unroll
    for (int i = 0; i < 2; ++i) {
        const int r = row0 + wm * 32 + i * 16 + (lane >> 2);
#pragma unroll
        for (int j = 0; j < 4; ++j) {
            const int c = col0 + wn * 32 + j * 8 + ((lane & 3) << 1);
            const float b0 = __ldg(&bias[c]);
            const float b1 = __ldg(&bias[c + 1]);
            float2 v0, v1;
            v0.x = acc[i][j][0] + b0; v0.y = acc[i][j][1] + b1;
            v1.x = acc[i][j][2] + b0; v1.y = acc[i][j][3] + b1;
            *(float2*)&C[(size_t)r * N + c]       = v0;
            *(float2*)&C[(size_t)(r + 8) * N + c] = v1;
        }
    }
}

// ---------------- TF32 tensor-core flash attention ---------------------------
// 256 threads / 8 warps. Warp owns 16 q-rows (1 m16 tile). BC=64 keys/tile.
// k-dim permutation pi(j)=2j, pi(j+4)=2j+1 on both QK and PV mmas.
#define FBR 128
#define FBC 64

__global__ __launch_bounds__(256, 2)
void flash_attn_tc_kernel(const float* __restrict__ Q,
                          const float* __restrict__ Km,
                          const float* __restrict__ V,
                          float* __restrict__ O)
{
    __shared__ uint2 kfrag[8 * 8 * 32];   // 16 KB
    __shared__ uint2 vfrag[8 * 8 * 32];   // 16 KB

    const int tid  = threadIdx.x;
    const int lane = tid & 31;
    const int warp = tid >> 5;        // 0..7
    const int g    = lane >> 2;
    const int j    = lane & 3;

    const int q0 = blockIdx.x * FBR;
    const int bh = blockIdx.y;
    const int b  = bh >> 4;
    const int h  = bh & 15;
    const size_t base = (size_t)b * SEQ * D_MODEL + (size_t)h * HEAD_DIM;

    const float c1 = 0.18033688011112042f;  // (1/sqrt(64)) * log2(e)

    // ---- Q frags in registers, pre-scaled, tf32 ----
    uint32_t qf[8][4];
    const int row = q0 + warp * 16 + g;
    {
        const float* qp = Q + base + (size_t)row * D_MODEL;
#pragma unroll
        for (int kk = 0; kk < 8; ++kk) {
            float2 lo = *(const float2*)&qp[kk * 8 + 2 * j];
            float2 hi = *(const float2*)&qp[(size_t)8 * D_MODEL + kk * 8 + 2 * j];
            qf[kk][0] = f2tf32(lo.x * c1);
            qf[kk][2] = f2tf32(lo.y * c1);
            qf[kk][1] = f2tf32(hi.x * c1);
            qf[kk][3] = f2tf32(hi.y * c1);
        }
    }

    float accO[8][4];
#pragma unroll
    for (int t = 0; t < 8; ++t)
#pragma unroll
        for (int e = 0; e < 4; ++e) accO[t][e] = 0.f;

    float mrun[2] = {-1e30f, -1e30f};
    float lrun[2] = {0.f, 0.f};

    for (int k0 = 0; k0 < SEQ; k0 += FBC) {
        __syncthreads();
        // ---- cooperative canonical-frag load of K and V ----
#pragma unroll
        for (int i = 0; i < 8; ++i) {
            const int f  = tid + i * 256;
            const int kk = f >> 8;
            const int tt = (f >> 5) & 7;
            const int ln = f & 31;
            const int jj = ln & 3;
            const int gg = ln >> 2;
            {
                const float* kp = Km + base + (size_t)(k0 + tt * 8 + gg) * D_MODEL
                                  + kk * 8 + 2 * jj;
                float2 v = *(const float2*)kp;
                kfrag[f] = make_uint2(f2tf32(v.x), f2tf32(v.y));
            }
            {
                const size_t off = base + (size_t)(k0 + kk * 8 + 2 * jj) * D_MODEL
                                   + tt * 8 + gg;
                float v0 = __ldg(V + off);
                float v1 = __ldg(V + off + D_MODEL);
                vfrag[f] = make_uint2(f2tf32(v0), f2tf32(v1));
            }
        }
        __syncthreads();

        // ---- S = (Q*c1) @ K^T ----
        float accS[8][4];
#pragma unroll
        for (int t = 0; t < 8; ++t)
#pragma unroll
            for (int e = 0; e < 4; ++e) accS[t][e] = 0.f;

#pragma unroll
        for (int t = 0; t < 8; ++t) {
#pragma unroll
            for (int kk = 0; kk < 8; ++kk) {
                uint2 kb = kfrag[(kk * 8 + t) * 32 + lane];
                MMA_TF32(accS[t][0], accS[t][1], accS[t][2], accS[t][3],
                         qf[kk][0], qf[kk][1], qf[kk][2], qf[kk][3],
                         kb.x, kb.y);
            }
        }

        // ---- online softmax (base-2) ----
#pragma unroll
        for (int hh = 0; hh < 2; ++hh) {
            const int e0 = 2 * hh;
            float lm = -1e30f;
#pragma unroll
            for (int t = 0; t < 8; ++t)
                lm = fmaxf(lm, fmaxf(accS[t][e0], accS[t][e0 + 1]));
            lm = fmaxf(lm, __shfl_xor_sync(0xffffffffu, lm, 1));
            lm = fmaxf(lm, __shfl_xor_sync(0xffffffffu, lm, 2));
            const float mnew = fmaxf(mrun[hh], lm);
            const float corr = ex2(mrun[hh] - mnew);
            mrun[hh] = mnew;
            float ls = 0.f;
#pragma unroll
            for (int t = 0; t < 8; ++t) {
                float p0 = ex2(accS[t][e0]     - mnew);
                float p1 = ex2(accS[t][e0 + 1] - mnew);
                accS[t][e0]     = p0;
                accS[t][e0 + 1] = p1;
                ls += p0 + p1;
            }
            ls += __shfl_xor_sync(0xffffffffu, ls, 1);
            ls += __shfl_xor_sync(0xffffffffu, ls, 2);
            lrun[hh] = lrun[hh] * corr + ls;
#pragma unroll
            for (int t = 0; t < 8; ++t) {
                accO[t][e0]     *= corr;
                accO[t][e0 + 1] *= corr;
            }
        }

        // ---- O += P @ V  (P A-frag = S C-frag rename) ----
#pragma unroll
        for (int kk = 0; kk < 8; ++kk) {
            uint32_t pf[4];
            pf[0] = f2tf32(accS[kk][0]);
            pf[1] = f2tf32(accS[kk][2]);
            pf[2] = f2tf32(accS[kk][1]);
            pf[3] = f2tf32(accS[kk][3]);
#pragma unroll
            for (int t = 0; t < 8; ++t) {
                uint2 vb = vfrag[(kk * 8 + t) * 32 + lane];
                MMA_TF32(accO[t][0], accO[t][1], accO[t][2], accO[t][3],
                         pf[0], pf[1], pf[2], pf[3],
                         vb.x, vb.y);
            }
        }
    }

    // ---- epilogue ----
    {
        const float inv0 = 1.f / lrun[0];
        const float inv1 = 1.f / lrun[1];
        float* op0 = O + base + (size_t)row * D_MODEL;
        float* op1 = op0 + (size_t)8 * D_MODEL;
#pragma unroll
        for (int t = 0; t < 8; ++t) {
            const int c = t * 8 + 2 * j;
            float2 v0, v1;
            v0.x = accO[t][0] * inv0; v0.y = accO[t][1] * inv0;
            v1.x = accO[t][2] * inv1; v1.y = accO[t][3] * inv1;
            *(float2*)&op0[c] = v0;
            *(float2*)&op1[c] = v1;
        }
    }
}

// ---------------- launch ----------------------------------------------------
extern "C" void kernel_launch(void* const* d_in, const int* in_sizes, int n_in,
                              void* d_out, int out_size)
{
    const float* query = (const float*)d_in[0];
    const float* key   = (const float*)d_in[1];
    const float* value = (const float*)d_in[2];
    const float* Wq    = (const float*)d_in[3];
    const float* bq    = (const float*)d_in[4];
    const float* Wk    = (const float*)d_in[5];
    const float* bk    = (const float*)d_in[6];
    const float* Wv    = (const float*)d_in[7];
    const float* bv    = (const float*)d_in[8];
    const float* Wo    = (const float*)d_in[9];
    const float* bo    = (const float*)d_in[10];
    float* out = (float*)d_out;

    float *pq, *pk, *pv, *pa;
    cudaGetSymbolAddress((void**)&pq, g_q);
    cudaGetSymbolAddress((void**)&pk, g_k);
    cudaGetSymbolAddress((void**)&pv, g_v);
    cudaGetSymbolAddress((void**)&pa, g_attn);

    dim3 gblk(D_MODEL / GBN, MTOT / GBM);   // 16 x 64
    dim3 gthr(256);

    gemm_tf32_kernel<<<gblk, gthr>>>(query, Wq, bq, pq, MTOT, D_MODEL, D_MODEL);
    gemm_tf32_kernel<<<gblk, gthr>>>(key,   Wk, bk, pk, MTOT, D_MODEL, D_MODEL);
    gemm_tf32_kernel<<<gblk, gthr>>>(value, Wv, bv, pv, MTOT, D_MODEL, D_MODEL);

    dim3 ablk(SEQ / FBR, BATCH * NUM_HEADS);  // 16 x 64
    flash_attn_tc_kernel<<<ablk, 256>>>(pq, pk, pv, pa);

    gemm_tf32_kernel<<<gblk, gthr>>>(pa, Wo, bo, out, MTOT, D_MODEL, D_MODEL);
}

// round 8
// speedup vs baseline: 1.4672x; 1.4672x over previous
#include <cuda_runtime.h>
#include <cstdint>

#define D_MODEL 1024
#define NUM_HEADS 16
#define HEAD_DIM 64
#define BATCH 4
#define SEQ 2048
#define MTOT (BATCH*SEQ)

// ---------------- scratch (device globals: no allocs allowed) ----------------
__device__ float g_q[(size_t)MTOT * D_MODEL];
__device__ float g_k[(size_t)MTOT * D_MODEL];
__device__ float g_v[(size_t)MTOT * D_MODEL];
__device__ float g_attn[(size_t)MTOT * D_MODEL];

// ---------------- helpers ----------------------------------------------------
__device__ __forceinline__ uint32_t f2tf32(float x) {
    uint32_t r;
    asm("cvt.rna.tf32.f32 %0, %1;" : "=r"(r) : "f"(x));
    return r;
}
__device__ __forceinline__ float ex2(float x) {
    float y;
    asm("ex2.approx.f32 %0, %1;" : "=f"(y) : "f"(x));
    return y;
}
__device__ __forceinline__ void cpa8(uint32_t dst, const void* src) {
    asm volatile("cp.async.ca.shared.global [%0], [%1], 8;" :: "r"(dst), "l"(src));
}
__device__ __forceinline__ void cpa4(uint32_t dst, const void* src) {
    asm volatile("cp.async.ca.shared.global [%0], [%1], 4;" :: "r"(dst), "l"(src));
}
#define CPA_COMMIT() asm volatile("cp.async.commit_group;" ::: "memory")
#define CPA_WAIT0()  asm volatile("cp.async.wait_group 0;" ::: "memory")

#define LDMATRIX_X4(R0, R1, R2, R3, addr)                                       \
    asm volatile("ldmatrix.sync.aligned.m8n8.x4.shared.b16 {%0,%1,%2,%3}, [%4];" \
                 : "=r"(R0), "=r"(R1), "=r"(R2), "=r"(R3) : "r"(addr))

#define MMA_TF32(C0, C1, C2, C3, A0, A1, A2, A3, B0, B1)                        \
    asm volatile("mma.sync.aligned.m16n8k8.row.col.f32.tf32.tf32.f32 "          \
                 "{%0,%1,%2,%3},{%4,%5,%6,%7},{%8,%9},{%0,%1,%2,%3};"           \
                 : "+f"(C0), "+f"(C1), "+f"(C2), "+f"(C3)                       \
                 : "r"(A0), "r"(A1), "r"(A2), "r"(A3), "r"(B0), "r"(B1))

// ---------------- TF32 tensor-core GEMM (R3-proven version) ------------------
// BM=128, BN=64, BK=16. 8 warps 4(m)x2(n), warp tile 32x32. Single-buffered.
// ROUND: round outputs to tf32 (for Q/K/V scratch feeding flash attention).
#define GBM 128
#define GBN 64
#define GBK 16
#define SA 20
#define SW 20

template<bool ROUND>
__global__ __launch_bounds__(256, 2)
void gemm_tf32_kernel(const float* __restrict__ A,
                      const float* __restrict__ W,
                      const float* __restrict__ bias,
                      float* __restrict__ C,
                      int M, int N, int K)
{
    __shared__ float As[GBM * SA];
    __shared__ float Ws[GBN * SW];

    const int tid  = threadIdx.x;
    const int lane = tid & 31;
    const int wid  = tid >> 5;
    const int wm   = wid >> 1;
    const int wn   = wid & 1;
    const int row0 = blockIdx.y * GBM;
    const int col0 = blockIdx.x * GBN;

    const int ar  = tid >> 2;
    const int akq = (tid & 3) << 2;
    const int wnx = tid & 63;
    const int wkg = (tid >> 6) << 2;

    const int lj = lane >> 3;
    const int lr = lane & 7;
    const uint32_t as_base = (uint32_t)__cvta_generic_to_shared(As);
    const uint32_t ws_base = (uint32_t)__cvta_generic_to_shared(Ws);
    uint32_t a_addr[2], b_addr[2];
#pragma unroll
    for (int i = 0; i < 2; ++i)
        a_addr[i] = as_base + (((wm * 32 + i * 16 + lr + 8 * (lj & 1)) * SA
                               + 4 * (lj >> 1)) << 2);
#pragma unroll
    for (int t = 0; t < 2; ++t)
        b_addr[t] = ws_base + (((wn * 32 + t * 16 + lr + 8 * (lj >> 1)) * SW
                               + 4 * (lj & 1)) << 2);

    float acc[2][4][4];
#pragma unroll
    for (int i = 0; i < 2; ++i)
#pragma unroll
        for (int j = 0; j < 4; ++j)
#pragma unroll
            for (int e = 0; e < 4; ++e) acc[i][j][e] = 0.f;

    const float* Ap0 = A + (size_t)(row0 + ar) * K + akq;
    const float* Ap1 = A + (size_t)(row0 + 64 + ar) * K + akq;
    const float* Wp  = W + (size_t)wkg * N + col0 + wnx;

    float4 pa0, pa1;
    float pw0, pw1, pw2, pw3;

    pa0 = *(const float4*)Ap0;
    pa1 = *(const float4*)Ap1;
    pw0 = Wp[0]; pw1 = Wp[(size_t)N]; pw2 = Wp[(size_t)2 * N]; pw3 = Wp[(size_t)3 * N];

    {
        float4 s0, s1, sw;
        s0.x = __uint_as_float(f2tf32(pa0.x)); s0.y = __uint_as_float(f2tf32(pa0.y));
        s0.z = __uint_as_float(f2tf32(pa0.z)); s0.w = __uint_as_float(f2tf32(pa0.w));
        s1.x = __uint_as_float(f2tf32(pa1.x)); s1.y = __uint_as_float(f2tf32(pa1.y));
        s1.z = __uint_as_float(f2tf32(pa1.z)); s1.w = __uint_as_float(f2tf32(pa1.w));
        sw.x = __uint_as_float(f2tf32(pw0));   sw.y = __uint_as_float(f2tf32(pw1));
        sw.z = __uint_as_float(f2tf32(pw2));   sw.w = __uint_as_float(f2tf32(pw3));
        *(float4*)&As[ar * SA + akq]        = s0;
        *(float4*)&As[(64 + ar) * SA + akq] = s1;
        *(float4*)&Ws[wnx * SW + wkg]       = sw;
    }
    __syncthreads();

    for (int k0 = 0; k0 < K; k0 += GBK) {
        const bool has_next = (k0 + GBK) < K;
        if (has_next) {
            pa0 = *(const float4*)(Ap0 + k0 + GBK);
            pa1 = *(const float4*)(Ap1 + k0 + GBK);
            const float* wp = Wp + (size_t)(k0 + GBK) * N;
            pw0 = wp[0]; pw1 = wp[(size_t)N]; pw2 = wp[(size_t)2 * N]; pw3 = wp[(size_t)3 * N];
        }

#pragma unroll
        for (int ks = 0; ks < GBK; ks += 8) {
            uint32_t a[2][4], bq[2][4];
            LDMATRIX_X4(a[0][0], a[0][1], a[0][2], a[0][3], a_addr[0] + (ks << 2));
            LDMATRIX_X4(a[1][0], a[1][1], a[1][2], a[1][3], a_addr[1] + (ks << 2));
            LDMATRIX_X4(bq[0][0], bq[0][1], bq[0][2], bq[0][3], b_addr[0] + (ks << 2));
            LDMATRIX_X4(bq[1][0], bq[1][1], bq[1][2], bq[1][3], b_addr[1] + (ks << 2));
#pragma unroll
            for (int i = 0; i < 2; ++i) {
                MMA_TF32(acc[i][0][0], acc[i][0][1], acc[i][0][2], acc[i][0][3],
                         a[i][0], a[i][1], a[i][2], a[i][3], bq[0][0], bq[0][1]);
                MMA_TF32(acc[i][1][0], acc[i][1][1], acc[i][1][2], acc[i][1][3],
                         a[i][0], a[i][1], a[i][2], a[i][3], bq[0][2], bq[0][3]);
                MMA_TF32(acc[i][2][0], acc[i][2][1], acc[i][2][2], acc[i][2][3],
                         a[i][0], a[i][1], a[i][2], a[i][3], bq[1][0], bq[1][1]);
                MMA_TF32(acc[i][3][0], acc[i][3][1], acc[i][3][2], acc[i][3][3],
                         a[i][0], a[i][1], a[i][2], a[i][3], bq[1][2], bq[1][3]);
            }
        }

        __syncthreads();
        if (has_next) {
            float4 s0, s1, sw;
            s0.x = __uint_as_float(f2tf32(pa0.x)); s0.y = __uint_as_float(f2tf32(pa0.y));
            s0.z = __uint_as_float(f2tf32(pa0.z)); s0.w = __uint_as_float(f2tf32(pa0.w));
            s1.x = __uint_as_float(f2tf32(pa1.x)); s1.y = __uint_as_float(f2tf32(pa1.y));
            s1.z = __uint_as_float(f2tf32(pa1.z)); s1.w = __uint_as_float(f2tf32(pa1.w));
            sw.x = __uint_as_float(f2tf32(pw0));   sw.y = __uint_as_float(f2tf32(pw1));
            sw.z = __uint_as_float(f2tf32(pw2));   sw.w = __uint_as_float(f2tf32(pw3));
            *(float4*)&As[ar * SA + akq]        = s0;
            *(float4*)&As[(64 + ar) * SA + akq] = s1;
            *(float4*)&Ws[wnx * SW + wkg]       = sw;
            __syncthreads();
        }
    }

#pragma unroll
    for (int i = 0; i < 2; ++i) {
        const int r = row0 + wm * 32 + i * 16 + (lane >> 2);
#pragma unroll
        for (int j = 0; j < 4; ++j) {
            const int c = col0 + wn * 32 + j * 8 + ((lane & 3) << 1);
            const float b0 = __ldg(&bias[c]);
            const float b1 = __ldg(&bias[c + 1]);
            float2 v0, v1;
            v0.x = acc[i][j][0] + b0; v0.y = acc[i][j][1] + b1;
            v1.x = acc[i][j][2] + b0; v1.y = acc[i][j][3] + b1;
            if (ROUND) {
                v0.x = __uint_as_float(f2tf32(v0.x));
                v0.y = __uint_as_float(f2tf32(v0.y));
                v1.x = __uint_as_float(f2tf32(v1.x));
                v1.y = __uint_as_float(f2tf32(v1.y));
            }
            *(float2*)&C[(size_t)r * N + c]       = v0;
            *(float2*)&C[(size_t)(r + 8) * N + c] = v1;
        }
    }
}

// ---------------- TF32 tensor-core flash attention ---------------------------
// 128 threads / 4 warps; warp owns 32 q-rows (2 m16 tiles). BC=64 keys/tile.
// K/V in gmem are PRE-ROUNDED tf32 -> loader is pure cp.async copies into
// double-buffered canonical frag layout. QK loop kk-outer for indep accum chains.
#define FBR 128
#define FBC 64
#define FTILES (SEQ / FBC)

__global__ __launch_bounds__(128)
void flash_attn_tc_kernel(const float* __restrict__ Q,
                          const float* __restrict__ Km,
                          const float* __restrict__ V,
                          float* __restrict__ O)
{
    extern __shared__ uint2 fsm[];            // [2][2048] K then [2][2048] V
    uint2* kbuf[2] = { fsm,        fsm + 2048 };
    uint2* vbuf[2] = { fsm + 4096, fsm + 6144 };
    const uint32_t smem_u32 = (uint32_t)__cvta_generic_to_shared(fsm);

    const int tid  = threadIdx.x;
    const int lane = tid & 31;
    const int warp = tid >> 5;
    const int g    = lane >> 2;
    const int j    = lane & 3;

    const int q0 = blockIdx.x * FBR;
    const int bh = blockIdx.y;
    const int b  = bh >> 4;
    const int h  = bh & 15;
    const size_t base = (size_t)b * SEQ * D_MODEL + (size_t)h * HEAD_DIM;

    const float c1 = 0.18033688011112042f;  // (1/sqrt(64)) * log2(e)

    // precomputed loader indices (16 frag-slots per thread)
    // f = tid + i*128 ; kk=f>>8, tt=(f>>5)&7, ln=f&31, jj=ln&3, gg=ln>>2
    // issue tile loads into buffer `bf`
    auto issue_tile = [&](int bf, int k0) {
#pragma unroll
        for (int i = 0; i < 16; ++i) {
            const int f  = tid + i * 128;
            const int kk = f >> 8;
            const int tt = (f >> 5) & 7;
            const int ln = f & 31;
            const int jj = ln & 3;
            const int gg = ln >> 2;
            // K frag: key = k0+tt*8+gg, d = kk*8+2jj (contiguous 8B)
            cpa8(smem_u32 + (bf * 2048 + f) * 8,
                 Km + base + (size_t)(k0 + tt * 8 + gg) * D_MODEL + kk * 8 + 2 * jj);
            // V frag: keys k0+kk*8+2jj(+1), d = tt*8+gg (two strided 4B)
            const float* vp = V + base + (size_t)(k0 + kk * 8 + 2 * jj) * D_MODEL
                              + tt * 8 + gg;
            const uint32_t vd = smem_u32 + (4096 + bf * 2048 + f) * 8;
            cpa4(vd,     vp);
            cpa4(vd + 4, vp + D_MODEL);
        }
        CPA_COMMIT();
    };

    // ---- Q frags in registers, pre-scaled, tf32 ----
    uint32_t qf[2][8][4];
#pragma unroll
    for (int m = 0; m < 2; ++m) {
        const int row = q0 + warp * 32 + m * 16 + g;
        const float* qp = Q + base + (size_t)row * D_MODEL;
#pragma unroll
        for (int kk = 0; kk < 8; ++kk) {
            float2 lo = *(const float2*)&qp[kk * 8 + 2 * j];
            float2 hi = *(const float2*)&qp[(size_t)8 * D_MODEL + kk * 8 + 2 * j];
            qf[m][kk][0] = f2tf32(lo.x * c1);
            qf[m][kk][2] = f2tf32(lo.y * c1);
            qf[m][kk][1] = f2tf32(hi.x * c1);
            qf[m][kk][3] = f2tf32(hi.y * c1);
        }
    }

    float accO[2][8][4];
#pragma unroll
    for (int m = 0; m < 2; ++m)
#pragma unroll
        for (int t = 0; t < 8; ++t)
#pragma unroll
            for (int e = 0; e < 4; ++e) accO[m][t][e] = 0.f;

    float mrun[2][2] = {{-1e30f, -1e30f}, {-1e30f, -1e30f}};
    float lrun[2][2] = {{0.f, 0.f}, {0.f, 0.f}};

    issue_tile(0, 0);   // prologue

    for (int ti = 0; ti < FTILES; ++ti) {
        const int cur = ti & 1;
        CPA_WAIT0();          // cur buffer's cp.asyncs done (this thread)
        __syncthreads();      // all threads' loads done + prev compute on nxt done
        if (ti + 1 < FTILES)
            issue_tile(cur ^ 1, (ti + 1) * FBC);   // overlap with compute below

        const uint2* kf = kbuf[cur];
        const uint2* vf = vbuf[cur];

        // ---- S = (Q*c1) @ K^T   (kk outer: independent accumulator chains) --
        float accS[2][8][4];
#pragma unroll
        for (int m = 0; m < 2; ++m)
#pragma unroll
            for (int t = 0; t < 8; ++t)
#pragma unroll
                for (int e = 0; e < 4; ++e) accS[m][t][e] = 0.f;

#pragma unroll
        for (int kk = 0; kk < 8; ++kk) {
#pragma unroll
            for (int t = 0; t < 8; ++t) {
                uint2 kb = kf[(kk * 8 + t) * 32 + lane];
#pragma unroll
                for (int m = 0; m < 2; ++m) {
                    MMA_TF32(accS[m][t][0], accS[m][t][1], accS[m][t][2], accS[m][t][3],
                             qf[m][kk][0], qf[m][kk][1], qf[m][kk][2], qf[m][kk][3],
                             kb.x, kb.y);
                }
            }
        }

        // ---- online softmax (base-2) ----
#pragma unroll
        for (int m = 0; m < 2; ++m) {
#pragma unroll
            for (int hh = 0; hh < 2; ++hh) {
                const int e0 = 2 * hh;
                float lm = -1e30f;
#pragma unroll
                for (int t = 0; t < 8; ++t)
                    lm = fmaxf(lm, fmaxf(accS[m][t][e0], accS[m][t][e0 + 1]));
                lm = fmaxf(lm, __shfl_xor_sync(0xffffffffu, lm, 1));
                lm = fmaxf(lm, __shfl_xor_sync(0xffffffffu, lm, 2));
                const float mnew = fmaxf(mrun[m][hh], lm);
                const float corr = ex2(mrun[m][hh] - mnew);
                mrun[m][hh] = mnew;
                float ls = 0.f;
#pragma unroll
                for (int t = 0; t < 8; ++t) {
                    float p0 = ex2(accS[m][t][e0]     - mnew);
                    float p1 = ex2(accS[m][t][e0 + 1] - mnew);
                    accS[m][t][e0]     = p0;
                    accS[m][t][e0 + 1] = p1;
                    ls += p0 + p1;
                }
                ls += __shfl_xor_sync(0xffffffffu, ls, 1);
                ls += __shfl_xor_sync(0xffffffffu, ls, 2);
                lrun[m][hh] = lrun[m][hh] * corr + ls;
#pragma unroll
                for (int t = 0; t < 8; ++t) {
                    accO[m][t][e0]     *= corr;
                    accO[m][t][e0 + 1] *= corr;
                }
            }
        }

        // ---- O += P @ V  (P A-frag = S C-frag rename) ----
#pragma unroll
        for (int kk = 0; kk < 8; ++kk) {
            uint32_t pf[2][4];
#pragma unroll
            for (int m = 0; m < 2; ++m) {
                pf[m][0] = f2tf32(accS[m][kk][0]);
                pf[m][1] = f2tf32(accS[m][kk][2]);
                pf[m][2] = f2tf32(accS[m][kk][1]);
                pf[m][3] = f2tf32(accS[m][kk][3]);
            }
#pragma unroll
            for (int t = 0; t < 8; ++t) {
                uint2 vb = vf[(kk * 8 + t) * 32 + lane];
#pragma unroll
                for (int m = 0; m < 2; ++m) {
                    MMA_TF32(accO[m][t][0], accO[m][t][1], accO[m][t][2], accO[m][t][3],
                             pf[m][0], pf[m][1], pf[m][2], pf[m][3],
                             vb.x, vb.y);
                }
            }
        }
    }

    // ---- epilogue ----
#pragma unroll
    for (int m = 0; m < 2; ++m) {
        const int row = q0 + warp * 32 + m * 16 + g;
        const float inv0 = 1.f / lrun[m][0];
        const float inv1 = 1.f / lrun[m][1];
        float* op0 = O + base + (size_t)row * D_MODEL;
        float* op1 = op0 + (size_t)8 * D_MODEL;
#pragma unroll
        for (int t = 0; t < 8; ++t) {
            const int c = t * 8 + 2 * j;
            float2 v0, v1;
            v0.x = accO[m][t][0] * inv0; v0.y = accO[m][t][1] * inv0;
            v1.x = accO[m][t][2] * inv1; v1.y = accO[m][t][3] * inv1;
            *(float2*)&op0[c] = v0;
            *(float2*)&op1[c] = v1;
        }
    }
}

// ---------------- launch ----------------------------------------------------
extern "C" void kernel_launch(void* const* d_in, const int* in_sizes, int n_in,
                              void* d_out, int out_size)
{
    const float* query = (const float*)d_in[0];
    const float* key   = (const float*)d_in[1];
    const float* value = (const float*)d_in[2];
    const float* Wq    = (const float*)d_in[3];
    const float* bq    = (const float*)d_in[4];
    const float* Wk    = (const float*)d_in[5];
    const float* bk    = (const float*)d_in[6];
    const float* Wv    = (const float*)d_in[7];
    const float* bv    = (const float*)d_in[8];
    const float* Wo    = (const float*)d_in[9];
    const float* bo    = (const float*)d_in[10];
    float* out = (float*)d_out;

    float *pq, *pk, *pv, *pa;
    cudaGetSymbolAddress((void**)&pq, g_q);
    cudaGetSymbolAddress((void**)&pk, g_k);
    cudaGetSymbolAddress((void**)&pv, g_v);
    cudaGetSymbolAddress((void**)&pa, g_attn);

    static bool attr_done = false;
    if (!attr_done) {
        cudaFuncSetAttribute(flash_attn_tc_kernel,
                             cudaFuncAttributeMaxDynamicSharedMemorySize, 65536);
        attr_done = true;
    }

    dim3 gblk(D_MODEL / GBN, MTOT / GBM);   // 16 x 64
    dim3 gthr(256);

    gemm_tf32_kernel<true><<<gblk, gthr>>>(query, Wq, bq, pq, MTOT, D_MODEL, D_MODEL);
    gemm_tf32_kernel<true><<<gblk, gthr>>>(key,   Wk, bk, pk, MTOT, D_MODEL, D_MODEL);
    gemm_tf32_kernel<true><<<gblk, gthr>>>(value, Wv, bv, pv, MTOT, D_MODEL, D_MODEL);

    dim3 ablk(SEQ / FBR, BATCH * NUM_HEADS);  // 16 x 64
    flash_attn_tc_kernel<<<ablk, 128, 65536>>>(pq, pk, pv, pa);

    gemm_tf32_kernel<false><<<gblk, gthr>>>(pa, Wo, bo, out, MTOT, D_MODEL, D_MODEL);
}

// round 9
// speedup vs baseline: 1.8619x; 1.2690x over previous
#include <cuda_runtime.h>
#include <cstdint>

#define D_MODEL 1024
#define NUM_HEADS 16
#define HEAD_DIM 64
#define BATCH 4
#define SEQ 2048
#define MTOT (BATCH*SEQ)

// ---------------- scratch (device globals: no allocs allowed) ----------------
__device__ float g_q[(size_t)MTOT * D_MODEL];
__device__ float g_k[(size_t)MTOT * D_MODEL];
__device__ float g_v[(size_t)MTOT * D_MODEL];
__device__ float g_attn[(size_t)MTOT * D_MODEL];

// ---------------- helpers ----------------------------------------------------
__device__ __forceinline__ uint32_t f2tf32(float x) {
    uint32_t r;
    asm("cvt.rna.tf32.f32 %0, %1;" : "=r"(r) : "f"(x));
    return r;
}
__device__ __forceinline__ float ex2(float x) {
    float y;
    asm("ex2.approx.f32 %0, %1;" : "=f"(y) : "f"(x));
    return y;
}
__device__ __forceinline__ void cpa8(uint32_t dst, const void* src) {
    asm volatile("cp.async.ca.shared.global [%0], [%1], 8;" :: "r"(dst), "l"(src));
}
__device__ __forceinline__ void cpa4(uint32_t dst, const void* src) {
    asm volatile("cp.async.ca.shared.global [%0], [%1], 4;" :: "r"(dst), "l"(src));
}
#define CPA_COMMIT() asm volatile("cp.async.commit_group;" ::: "memory")
#define CPA_WAIT0()  asm volatile("cp.async.wait_group 0;" ::: "memory")

#define LDMATRIX_X4(R0, R1, R2, R3, addr)                                       \
    asm volatile("ldmatrix.sync.aligned.m8n8.x4.shared.b16 {%0,%1,%2,%3}, [%4];" \
                 : "=r"(R0), "=r"(R1), "=r"(R2), "=r"(R3) : "r"(addr))

#define MMA_TF32(C0, C1, C2, C3, A0, A1, A2, A3, B0, B1)                        \
    asm volatile("mma.sync.aligned.m16n8k8.row.col.f32.tf32.tf32.f32 "          \
                 "{%0,%1,%2,%3},{%4,%5,%6,%7},{%8,%9},{%0,%1,%2,%3};"           \
                 : "+f"(C0), "+f"(C1), "+f"(C2), "+f"(C3)                       \
                 : "r"(A0), "r"(A1), "r"(A2), "r"(A3), "r"(B0), "r"(B1))

// ---------------- TF32 tensor-core GEMM: C = A[M,K] @ W[K,N] + bias ----------
// BM=128, BN=128, BK=16. 8 warps 4(m)x2(n), warp tile 32x64. Single-buffered
// (R3-proven loop structure). ROUND: tf32-round outputs (Q/K/V scratch).
#define GBM 128
#define GBN 128
#define GBK 16
#define SA 20
#define SW 20

struct QKVArgs {
    const float* A[3];
    const float* W[3];
    const float* b[3];
    float*       C[3];
};

template<bool ROUND>
__device__ __forceinline__
void gemm_tf32_body(const float* __restrict__ A,
                    const float* __restrict__ W,
                    const float* __restrict__ bias,
                    float* __restrict__ C,
                    int M, int N, int K)
{
    __shared__ float As[GBM * SA];
    __shared__ float Ws[GBN * SW];

    const int tid  = threadIdx.x;
    const int lane = tid & 31;
    const int wid  = tid >> 5;
    const int wm   = wid >> 1;          // 0..3
    const int wn   = wid & 1;           // 0..1
    const int row0 = blockIdx.y * GBM;
    const int col0 = blockIdx.x * GBN;

    // A-tile loads: rows ar, ar+64; k-quad akq
    const int ar  = tid >> 2;
    const int akq = (tid & 3) << 2;
    // W-tile loads: n = wnx (0..127), k-rows wkg..wkg+7
    const int wnx = tid & 127;
    const int wkg = (tid >> 7) << 3;    // 0 or 8

    const int lj = lane >> 3;
    const int lr = lane & 7;
    const uint32_t as_base = (uint32_t)__cvta_generic_to_shared(As);
    const uint32_t ws_base = (uint32_t)__cvta_generic_to_shared(Ws);
    uint32_t a_addr[2], b_addr[4];
#pragma unroll
    for (int i = 0; i < 2; ++i)
        a_addr[i] = as_base + (((wm * 32 + i * 16 + lr + 8 * (lj & 1)) * SA
                               + 4 * (lj >> 1)) << 2);
#pragma unroll
    for (int t = 0; t < 4; ++t)
        b_addr[t] = ws_base + (((wn * 64 + t * 16 + lr + 8 * (lj >> 1)) * SW
                               + 4 * (lj & 1)) << 2);

    float acc[2][8][4];
#pragma unroll
    for (int i = 0; i < 2; ++i)
#pragma unroll
        for (int j = 0; j < 8; ++j)
#pragma unroll
            for (int e = 0; e < 4; ++e) acc[i][j][e] = 0.f;

    const float* Ap0 = A + (size_t)(row0 + ar) * K + akq;
    const float* Ap1 = A + (size_t)(row0 + 64 + ar) * K + akq;
    const float* Wp  = W + (size_t)wkg * N + col0 + wnx;

    float4 pa0, pa1;
    float pw[8];

    pa0 = *(const float4*)Ap0;
    pa1 = *(const float4*)Ap1;
#pragma unroll
    for (int r = 0; r < 8; ++r) pw[r] = Wp[(size_t)r * N];

    {
        float4 s0, s1;
        s0.x = __uint_as_float(f2tf32(pa0.x)); s0.y = __uint_as_float(f2tf32(pa0.y));
        s0.z = __uint_as_float(f2tf32(pa0.z)); s0.w = __uint_as_float(f2tf32(pa0.w));
        s1.x = __uint_as_float(f2tf32(pa1.x)); s1.y = __uint_as_float(f2tf32(pa1.y));
        s1.z = __uint_as_float(f2tf32(pa1.z)); s1.w = __uint_as_float(f2tf32(pa1.w));
        *(float4*)&As[ar * SA + akq]        = s0;
        *(float4*)&As[(64 + ar) * SA + akq] = s1;
        float4 w0, w1;
        w0.x = __uint_as_float(f2tf32(pw[0])); w0.y = __uint_as_float(f2tf32(pw[1]));
        w0.z = __uint_as_float(f2tf32(pw[2])); w0.w = __uint_as_float(f2tf32(pw[3]));
        w1.x = __uint_as_float(f2tf32(pw[4])); w1.y = __uint_as_float(f2tf32(pw[5]));
        w1.z = __uint_as_float(f2tf32(pw[6])); w1.w = __uint_as_float(f2tf32(pw[7]));
        *(float4*)&Ws[wnx * SW + wkg]     = w0;
        *(float4*)&Ws[wnx * SW + wkg + 4] = w1;
    }
    __syncthreads();

    for (int k0 = 0; k0 < K; k0 += GBK) {
        const bool has_next = (k0 + GBK) < K;
        if (has_next) {
            pa0 = *(const float4*)(Ap0 + k0 + GBK);
            pa1 = *(const float4*)(Ap1 + k0 + GBK);
            const float* wp = Wp + (size_t)(k0 + GBK) * N;
#pragma unroll
            for (int r = 0; r < 8; ++r) pw[r] = wp[(size_t)r * N];
        }

#pragma unroll
        for (int ks = 0; ks < GBK; ks += 8) {
            uint32_t a[2][4], bq[4][4];
            LDMATRIX_X4(a[0][0], a[0][1], a[0][2], a[0][3], a_addr[0] + (ks << 2));
            LDMATRIX_X4(a[1][0], a[1][1], a[1][2], a[1][3], a_addr[1] + (ks << 2));
#pragma unroll
            for (int t = 0; t < 4; ++t)
                LDMATRIX_X4(bq[t][0], bq[t][1], bq[t][2], bq[t][3],
                            b_addr[t] + (ks << 2));
#pragma unroll
            for (int i = 0; i < 2; ++i) {
#pragma unroll
                for (int t = 0; t < 4; ++t) {
                    MMA_TF32(acc[i][2*t][0], acc[i][2*t][1], acc[i][2*t][2], acc[i][2*t][3],
                             a[i][0], a[i][1], a[i][2], a[i][3], bq[t][0], bq[t][1]);
                    MMA_TF32(acc[i][2*t+1][0], acc[i][2*t+1][1], acc[i][2*t+1][2], acc[i][2*t+1][3],
                             a[i][0], a[i][1], a[i][2], a[i][3], bq[t][2], bq[t][3]);
                }
            }
        }

        __syncthreads();
        if (has_next) {
            float4 s0, s1;
            s0.x = __uint_as_float(f2tf32(pa0.x)); s0.y = __uint_as_float(f2tf32(pa0.y));
            s0.z = __uint_as_float(f2tf32(pa0.z)); s0.w = __uint_as_float(f2tf32(pa0.w));
            s1.x = __uint_as_float(f2tf32(pa1.x)); s1.y = __uint_as_float(f2tf32(pa1.y));
            s1.z = __uint_as_float(f2tf32(pa1.z)); s1.w = __uint_as_float(f2tf32(pa1.w));
            *(float4*)&As[ar * SA + akq]        = s0;
            *(float4*)&As[(64 + ar) * SA + akq] = s1;
            float4 w0, w1;
            w0.x = __uint_as_float(f2tf32(pw[0])); w0.y = __uint_as_float(f2tf32(pw[1]));
            w0.z = __uint_as_float(f2tf32(pw[2])); w0.w = __uint_as_float(f2tf32(pw[3]));
            w1.x = __uint_as_float(f2tf32(pw[4])); w1.y = __uint_as_float(f2tf32(pw[5]));
            w1.z = __uint_as_float(f2tf32(pw[6])); w1.w = __uint_as_float(f2tf32(pw[7]));
            *(float4*)&Ws[wnx * SW + wkg]     = w0;
            *(float4*)&Ws[wnx * SW + wkg + 4] = w1;
            __syncthreads();
        }
    }

    // epilogue
#pragma unroll
    for (int i = 0; i < 2; ++i) {
        const int r = row0 + wm * 32 + i * 16 + (lane >> 2);
#pragma unroll
        for (int j = 0; j < 8; ++j) {
            const int c = col0 + wn * 64 + j * 8 + ((lane & 3) << 1);
            const float b0 = __ldg(&bias[c]);
            const float b1 = __ldg(&bias[c + 1]);
            float2 v0, v1;
            v0.x = acc[i][j][0] + b0; v0.y = acc[i][j][1] + b1;
            v1.x = acc[i][j][2] + b0; v1.y = acc[i][j][3] + b1;
            if (ROUND) {
                v0.x = __uint_as_float(f2tf32(v0.x));
                v0.y = __uint_as_float(f2tf32(v0.y));
                v1.x = __uint_as_float(f2tf32(v1.x));
                v1.y = __uint_as_float(f2tf32(v1.y));
            }
            *(float2*)&C[(size_t)r * N + c]       = v0;
            *(float2*)&C[(size_t)(r + 8) * N + c] = v1;
        }
    }
}

// fused Q/K/V projections: blockIdx.z selects the (A, W, bias, C) set
__global__ __launch_bounds__(256, 2)
void qkv_gemm_kernel(QKVArgs args, int M, int N, int K)
{
    const int z = blockIdx.z;
    gemm_tf32_body<true>(args.A[z], args.W[z], args.b[z], args.C[z], M, N, K);
}

__global__ __launch_bounds__(256, 2)
void out_gemm_kernel(const float* __restrict__ A, const float* __restrict__ W,
                     const float* __restrict__ bias, float* __restrict__ C,
                     int M, int N, int K)
{
    gemm_tf32_body<false>(A, W, bias, C, M, N, K);
}

// ---------------- TF32 tensor-core flash attention (R8-proven) ---------------
#define FBR 128
#define FBC 64
#define FTILES (SEQ / FBC)

__global__ __launch_bounds__(128)
void flash_attn_tc_kernel(const float* __restrict__ Q,
                          const float* __restrict__ Km,
                          const float* __restrict__ V,
                          float* __restrict__ O)
{
    extern __shared__ uint2 fsm[];            // [2][2048] K then [2][2048] V
    uint2* kbuf[2] = { fsm,        fsm + 2048 };
    uint2* vbuf[2] = { fsm + 4096, fsm + 6144 };
    const uint32_t smem_u32 = (uint32_t)__cvta_generic_to_shared(fsm);

    const int tid  = threadIdx.x;
    const int lane = tid & 31;
    const int warp = tid >> 5;
    const int g    = lane >> 2;
    const int j    = lane & 3;

    const int q0 = blockIdx.x * FBR;
    const int bh = blockIdx.y;
    const int b  = bh >> 4;
    const int h  = bh & 15;
    const size_t base = (size_t)b * SEQ * D_MODEL + (size_t)h * HEAD_DIM;

    const float c1 = 0.18033688011112042f;  // (1/sqrt(64)) * log2(e)

    auto issue_tile = [&](int bf, int k0) {
#pragma unroll
        for (int i = 0; i < 16; ++i) {
            const int f  = tid + i * 128;
            const int kk = f >> 8;
            const int tt = (f >> 5) & 7;
            const int ln = f & 31;
            const int jj = ln & 3;
            const int gg = ln >> 2;
            cpa8(smem_u32 + (bf * 2048 + f) * 8,
                 Km + base + (size_t)(k0 + tt * 8 + gg) * D_MODEL + kk * 8 + 2 * jj);
            const float* vp = V + base + (size_t)(k0 + kk * 8 + 2 * jj) * D_MODEL
                              + tt * 8 + gg;
            const uint32_t vd = smem_u32 + (4096 + bf * 2048 + f) * 8;
            cpa4(vd,     vp);
            cpa4(vd + 4, vp + D_MODEL);
        }
        CPA_COMMIT();
    };

    uint32_t qf[2][8][4];
#pragma unroll
    for (int m = 0; m < 2; ++m) {
        const int row = q0 + warp * 32 + m * 16 + g;
        const float* qp = Q + base + (size_t)row * D_MODEL;
#pragma unroll
        for (int kk = 0; kk < 8; ++kk) {
            float2 lo = *(const float2*)&qp[kk * 8 + 2 * j];
            float2 hi = *(const float2*)&qp[(size_t)8 * D_MODEL + kk * 8 + 2 * j];
            qf[m][kk][0] = f2tf32(lo.x * c1);
            qf[m][kk][2] = f2tf32(lo.y * c1);
            qf[m][kk][1] = f2tf32(hi.x * c1);
            qf[m][kk][3] = f2tf32(hi.y * c1);
        }
    }

    float accO[2][8][4];
#pragma unroll
    for (int m = 0; m < 2; ++m)
#pragma unroll
        for (int t = 0; t < 8; ++t)
#pragma unroll
            for (int e = 0; e < 4; ++e) accO[m][t][e] = 0.f;

    float mrun[2][2] = {{-1e30f, -1e30f}, {-1e30f, -1e30f}};
    float lrun[2][2] = {{0.f, 0.f}, {0.f, 0.f}};

    issue_tile(0, 0);

    for (int ti = 0; ti < FTILES; ++ti) {
        const int cur = ti & 1;
        CPA_WAIT0();
        __syncthreads();
        if (ti + 1 < FTILES)
            issue_tile(cur ^ 1, (ti + 1) * FBC);

        const uint2* kf = kbuf[cur];
        const uint2* vf = vbuf[cur];

        float accS[2][8][4];
#pragma unroll
        for (int m = 0; m < 2; ++m)
#pragma unroll
            for (int t = 0; t < 8; ++t)
#pragma unroll
                for (int e = 0; e < 4; ++e) accS[m][t][e] = 0.f;

#pragma unroll
        for (int kk = 0; kk < 8; ++kk) {
#pragma unroll
            for (int t = 0; t < 8; ++t) {
                uint2 kb = kf[(kk * 8 + t) * 32 + lane];
#pragma unroll
                for (int m = 0; m < 2; ++m) {
                    MMA_TF32(accS[m][t][0], accS[m][t][1], accS[m][t][2], accS[m][t][3],
                             qf[m][kk][0], qf[m][kk][1], qf[m][kk][2], qf[m][kk][3],
                             kb.x, kb.y);
                }
            }
        }

#pragma unroll
        for (int m = 0; m < 2; ++m) {
#pragma unroll
            for (int hh = 0; hh < 2; ++hh) {
                const int e0 = 2 * hh;
                float lm = -1e30f;
#pragma unroll
                for (int t = 0; t < 8; ++t)
                    lm = fmaxf(lm, fmaxf(accS[m][t][e0], accS[m][t][e0 + 1]));
                lm = fmaxf(lm, __shfl_xor_sync(0xffffffffu, lm, 1));
                lm = fmaxf(lm, __shfl_xor_sync(0xffffffffu, lm, 2));
                const float mnew = fmaxf(mrun[m][hh], lm);
                const float corr = ex2(mrun[m][hh] - mnew);
                mrun[m][hh] = mnew;
                float ls = 0.f;
#pragma unroll
                for (int t = 0; t < 8; ++t) {
                    float p0 = ex2(accS[m][t][e0]     - mnew);
                    float p1 = ex2(accS[m][t][e0 + 1] - mnew);
                    accS[m][t][e0]     = p0;
                    accS[m][t][e0 + 1] = p1;
                    ls += p0 + p1;
                }
                ls += __shfl_xor_sync(0xffffffffu, ls, 1);
                ls += __shfl_xor_sync(0xffffffffu, ls, 2);
                lrun[m][hh] = lrun[m][hh] * corr + ls;
#pragma unroll
                for (int t = 0; t < 8; ++t) {
                    accO[m][t][e0]     *= corr;
                    accO[m][t][e0 + 1] *= corr;
                }
            }
        }

#pragma unroll
        for (int kk = 0; kk < 8; ++kk) {
            uint32_t pf[2][4];
#pragma unroll
            for (int m = 0; m < 2; ++m) {
                pf[m][0] = f2tf32(accS[m][kk][0]);
                pf[m][1] = f2tf32(accS[m][kk][2]);
                pf[m][2] = f2tf32(accS[m][kk][1]);
                pf[m][3] = f2tf32(accS[m][kk][3]);
            }
#pragma unroll
            for (int t = 0; t < 8; ++t) {
                uint2 vb = vf[(kk * 8 + t) * 32 + lane];
#pragma unroll
                for (int m = 0; m < 2; ++m) {
                    MMA_TF32(accO[m][t][0], accO[m][t][1], accO[m][t][2], accO[m][t][3],
                             pf[m][0], pf[m][1], pf[m][2], pf[m][3],
                             vb.x, vb.y);
                }
            }
        }
    }

#pragma unroll
    for (int m = 0; m < 2; ++m) {
        const int row = q0 + warp * 32 + m * 16 + g;
        const float inv0 = 1.f / lrun[m][0];
        const float inv1 = 1.f / lrun[m][1];
        float* op0 = O + base + (size_t)row * D_MODEL;
        float* op1 = op0 + (size_t)8 * D_MODEL;
#pragma unroll
        for (int t = 0; t < 8; ++t) {
            const int c = t * 8 + 2 * j;
            float2 v0, v1;
            v0.x = accO[m][t][0] * inv0; v0.y = accO[m][t][1] * inv0;
            v1.x = accO[m][t][2] * inv1; v1.y = accO[m][t][3] * inv1;
            *(float2*)&op0[c] = v0;
            *(float2*)&op1[c] = v1;
        }
    }
}

// ---------------- launch ----------------------------------------------------
extern "C" void kernel_launch(void* const* d_in, const int* in_sizes, int n_in,
                              void* d_out, int out_size)
{
    const float* query = (const float*)d_in[0];
    const float* key   = (const float*)d_in[1];
    const float* value = (const float*)d_in[2];
    const float* Wq    = (const float*)d_in[3];
    const float* bq    = (const float*)d_in[4];
    const float* Wk    = (const float*)d_in[5];
    const float* bk    = (const float*)d_in[6];
    const float* Wv    = (const float*)d_in[7];
    const float* bv    = (const float*)d_in[8];
    const float* Wo    = (const float*)d_in[9];
    const float* bo    = (const float*)d_in[10];
    float* out = (float*)d_out;

    float *pq, *pk, *pv, *pa;
    cudaGetSymbolAddress((void**)&pq, g_q);
    cudaGetSymbolAddress((void**)&pk, g_k);
    cudaGetSymbolAddress((void**)&pv, g_v);
    cudaGetSymbolAddress((void**)&pa, g_attn);

    static bool attr_done = false;
    if (!attr_done) {
        cudaFuncSetAttribute(flash_attn_tc_kernel,
                             cudaFuncAttributeMaxDynamicSharedMemorySize, 65536);
        attr_done = true;
    }

    QKVArgs args;
    args.A[0] = query; args.W[0] = Wq; args.b[0] = bq; args.C[0] = pq;
    args.A[1] = key;   args.W[1] = Wk; args.b[1] = bk; args.C[1] = pk;
    args.A[2] = value; args.W[2] = Wv; args.b[2] = bv; args.C[2] = pv;

    dim3 qkvg(D_MODEL / GBN, MTOT / GBM, 3);   // 8 x 64 x 3
    qkv_gemm_kernel<<<qkvg, 256>>>(args, MTOT, D_MODEL, D_MODEL);

    dim3 ablk(SEQ / FBR, BATCH * NUM_HEADS);   // 16 x 64
    flash_attn_tc_kernel<<<ablk, 128, 65536>>>(pq, pk, pv, pa);

    dim3 og(D_MODEL / GBN, MTOT / GBM);        // 8 x 64
    out_gemm_kernel<<<og, 256>>>(pa, Wo, bo, out, MTOT, D_MODEL, D_MODEL);
}